// round 2
// baseline (speedup 1.0000x reference)
#include <cuda_runtime.h>
#include <cuda_bf16.h>
#include <math.h>

// TimeAwareScaledDotProduct: b=4, h=8, L=256, d=64
// energy[q,k] = (Q.(K[k]+tmK[q,k])) / sqrt(d) + attn_mask[q,k]; padded -> MASK_VAL
// A = softmax_k(energy)
// O[q,d] = sum_k A[q,k] * (V[k,d] + tmV[q,k,d])
// Output: [O (b,h,L,d) | A (b,h,L,L)] flattened.

#define L_DIM 256
#define D_DIM 64
#define MASK_VAL (-4294967295.0f)   // -2^32 + 1

__global__ __launch_bounds__(256, 6)
void taspd_kernel(const float* __restrict__ Q,
                  const float* __restrict__ K,
                  const float* __restrict__ V,
                  const float* __restrict__ tmK,
                  const float* __restrict__ tmV,
                  const float* __restrict__ attn_mask,
                  const unsigned char* __restrict__ pad_mask,
                  float* __restrict__ O,
                  float* __restrict__ A_out,
                  int H)
{
    const int q  = blockIdx.x;          // 0..L-1
    const int bh = blockIdx.y;          // 0..B*H-1
    const int b  = bh / H;

    const int tid   = threadIdx.x;      // 0..255
    const int wid   = tid >> 5;         // 0..7
    const int lane  = tid & 31;
    const int half  = lane >> 4;        // 0/1: which of the 2 k-rows this lane works on
    const int dlane = lane & 15;        // d-group within a k-row (4 floats each)

    __shared__ float sQ[D_DIM];
    __shared__ float sE[L_DIM];
    __shared__ float sPart[8][D_DIM];
    __shared__ float sRed[8];
    __shared__ float sBcast;

    // ---- load Q row ----
    const long long row_qd = (long long)(bh * L_DIM + q) * D_DIM;
    if (tid < D_DIM) sQ[tid] = Q[row_qd + tid];
    __syncthreads();

    const float4 qv = *(const float4*)&sQ[4 * dlane];

    const long long tm_row  = ((long long)(bh * L_DIM + q)) * L_DIM * D_DIM; // tmK/tmV row base
    const long long kv_base = (long long)bh * L_DIM * D_DIM;                 // K/V base
    const int kbase = wid * 32;

    // ---- phase 1: energy row (warp handles 32 k's, 2 per iteration) ----
    #pragma unroll 4
    for (int i = 0; i < 16; i++) {
        const int k = kbase + 2 * i + half;
        const float4 tk = *(const float4*)&tmK[tm_row  + (long long)k * D_DIM + 4 * dlane];
        const float4 kk = *(const float4*)&K  [kv_base + (long long)k * D_DIM + 4 * dlane];
        float p = qv.x * (tk.x + kk.x) + qv.y * (tk.y + kk.y)
                + qv.z * (tk.z + kk.z) + qv.w * (tk.w + kk.w);
        // reduce within 16-lane group
        p += __shfl_xor_sync(0xffffffffu, p, 8);
        p += __shfl_xor_sync(0xffffffffu, p, 4);
        p += __shfl_xor_sync(0xffffffffu, p, 2);
        p += __shfl_xor_sync(0xffffffffu, p, 1);
        if (dlane == 0) {
            float e = p * 0.125f + attn_mask[q * L_DIM + k];   // /sqrt(64)
            if (pad_mask[b * L_DIM + k]) e = MASK_VAL;
            sE[k] = e;
        }
    }
    __syncthreads();

    // ---- phase 2: softmax over k ----
    {
        float m = sE[tid];
        m = fmaxf(m, __shfl_xor_sync(0xffffffffu, m, 16));
        m = fmaxf(m, __shfl_xor_sync(0xffffffffu, m, 8));
        m = fmaxf(m, __shfl_xor_sync(0xffffffffu, m, 4));
        m = fmaxf(m, __shfl_xor_sync(0xffffffffu, m, 2));
        m = fmaxf(m, __shfl_xor_sync(0xffffffffu, m, 1));
        if (lane == 0) sRed[wid] = m;
        __syncthreads();
        if (tid == 0) {
            float mm = sRed[0];
            #pragma unroll
            for (int w = 1; w < 8; w++) mm = fmaxf(mm, sRed[w]);
            sBcast = mm;
        }
        __syncthreads();
    }
    const float rowmax = sBcast;
    float e = __expf(sE[tid] - rowmax);
    __syncthreads();   // protect sBcast reuse below
    {
        float s = e;
        s += __shfl_xor_sync(0xffffffffu, s, 16);
        s += __shfl_xor_sync(0xffffffffu, s, 8);
        s += __shfl_xor_sync(0xffffffffu, s, 4);
        s += __shfl_xor_sync(0xffffffffu, s, 2);
        s += __shfl_xor_sync(0xffffffffu, s, 1);
        if (lane == 0) sRed[wid] = s;
        __syncthreads();
        if (tid == 0) {
            float ss = 0.f;
            #pragma unroll
            for (int w = 0; w < 8; w++) ss += sRed[w];
            sBcast = 1.0f / ss;
        }
        __syncthreads();
    }
    const float a = e * sBcast;
    sE[tid] = a;
    if (A_out) {
        A_out[((long long)(bh * L_DIM + q)) * L_DIM + tid] = a;
    }
    __syncthreads();

    // ---- phase 3: output row (warp handles 32 k's, 2 per iteration) ----
    float4 acc = make_float4(0.f, 0.f, 0.f, 0.f);
    #pragma unroll 4
    for (int i = 0; i < 16; i++) {
        const int k = kbase + 2 * i + half;
        const float aw = sE[k];
        const float4 tv = *(const float4*)&tmV[tm_row  + (long long)k * D_DIM + 4 * dlane];
        const float4 vv = *(const float4*)&V  [kv_base + (long long)k * D_DIM + 4 * dlane];
        acc.x = fmaf(aw, vv.x + tv.x, acc.x);
        acc.y = fmaf(aw, vv.y + tv.y, acc.y);
        acc.z = fmaf(aw, vv.z + tv.z, acc.z);
        acc.w = fmaf(aw, vv.w + tv.w, acc.w);
    }
    // combine the two k-parity halves (same d-block)
    acc.x += __shfl_xor_sync(0xffffffffu, acc.x, 16);
    acc.y += __shfl_xor_sync(0xffffffffu, acc.y, 16);
    acc.z += __shfl_xor_sync(0xffffffffu, acc.z, 16);
    acc.w += __shfl_xor_sync(0xffffffffu, acc.w, 16);
    if (half == 0) {
        *(float4*)&sPart[wid][4 * dlane] = acc;
    }
    __syncthreads();

    if (tid < D_DIM) {
        float s = 0.f;
        #pragma unroll
        for (int w = 0; w < 8; w++) s += sPart[w][tid];
        O[row_qd + tid] = s;
    }
}

extern "C" void kernel_launch(void* const* d_in, const int* in_sizes, int n_in,
                              void* d_out, int out_size)
{
    const float* Q   = (const float*)d_in[0];
    const float* K   = (const float*)d_in[1];
    const float* V   = (const float*)d_in[2];
    const float* tmK = (const float*)d_in[3];
    const float* tmV = (const float*)d_in[4];
    const float* attn_mask = (const float*)d_in[5];
    const unsigned char* pad_mask = (const unsigned char*)d_in[6];

    const int L  = L_DIM;
    const int D  = D_DIM;
    const int BH = in_sizes[0] / (L * D);      // b*h
    const int B  = in_sizes[6] / L;            // padding_mask = (b, L)
    const int H  = BH / B;

    const long long O_elems = (long long)in_sizes[0];
    const long long A_elems = (long long)BH * L * L;

    float* O_out = (float*)d_out;
    float* A_out = ((long long)out_size >= O_elems + A_elems)
                       ? (float*)d_out + O_elems : nullptr;

    dim3 grid(L, BH);
    taspd_kernel<<<grid, 256>>>(Q, K, V, tmK, tmV, attn_mask, pad_mask,
                                O_out, A_out, H);
}

// round 7
// speedup vs baseline: 1.0877x; 1.0877x over previous
#include <cuda_runtime.h>
#include <cuda_bf16.h>
#include <math.h>

// TimeAwareScaledDotProduct: b=4, h=8, L=256, d=64
// energy[q,k] = (Q.(K[k]+tmK[q,k])) / sqrt(d) + attn_mask[q,k]; padded -> MASK_VAL
// A = softmax_k(energy)
// O[q,d] = sum_k A[q,k] * (V[k,d] + tmV[q,k,d])
// Output: [O (b,h,L,d) | A (b,h,L,L)] flattened.

#define L_DIM 256
#define D_DIM 64
#define MASK_VAL (-4294967295.0f)   // -2^32 + 1

__global__ __launch_bounds__(256, 6)
void taspd_kernel(const float* __restrict__ Q,
                  const float* __restrict__ K,
                  const float* __restrict__ V,
                  const float* __restrict__ tmK,
                  const float* __restrict__ tmV,
                  const float* __restrict__ attn_mask,
                  const unsigned char* __restrict__ pad_mask,
                  float* __restrict__ O,
                  float* __restrict__ A_out,
                  int H)
{
    const int q  = blockIdx.x;          // 0..L-1
    const int bh = blockIdx.y;          // 0..B*H-1
    const int b  = bh / H;

    const int tid  = threadIdx.x;       // 0..255
    const int wid  = tid >> 5;          // 0..7
    const int lane = tid & 31;

    __shared__ float sQ[D_DIM];
    __shared__ float sE[L_DIM];
    __shared__ float sPart[8][D_DIM];
    __shared__ float sRed[8];
    __shared__ float sBcast;

    // ---- load Q row ----
    const long long row_qd = (long long)(bh * L_DIM + q) * D_DIM;
    if (tid < D_DIM) sQ[tid] = Q[row_qd + tid];
    __syncthreads();

    const float q0 = sQ[2 * lane];
    const float q1 = sQ[2 * lane + 1];

    const long long tm_row  = ((long long)(bh * L_DIM + q)) * L_DIM * D_DIM;
    const long long kv_base = (long long)bh * L_DIM * D_DIM;
    const int kbase = wid * 32;

    // ---- phase 1: energy row (each warp: 32 consecutive k's) ----
    {
        const float2* pT = (const float2*)&tmK[tm_row  + (long long)kbase * D_DIM + 2 * lane];
        const float2* pK = (const float2*)&K  [kv_base + (long long)kbase * D_DIM + 2 * lane];
        #pragma unroll 4
        for (int i = 0; i < 32; i++) {
            const float2 tk = pT[i * (D_DIM / 2)];
            const float2 kk = pK[i * (D_DIM / 2)];
            float p = q0 * (tk.x + kk.x) + q1 * (tk.y + kk.y);
            p += __shfl_xor_sync(0xffffffffu, p, 16);
            p += __shfl_xor_sync(0xffffffffu, p, 8);
            p += __shfl_xor_sync(0xffffffffu, p, 4);
            p += __shfl_xor_sync(0xffffffffu, p, 2);
            p += __shfl_xor_sync(0xffffffffu, p, 1);
            if (lane == 0) {
                const int k = kbase + i;
                float e = p * 0.125f + attn_mask[q * L_DIM + k];   // /sqrt(64)
                if (pad_mask[b * L_DIM + k]) e = MASK_VAL;
                sE[k] = e;
            }
        }
    }
    __syncthreads();

    // ---- phase 2: softmax over k ----
    {
        float m = sE[tid];
        m = fmaxf(m, __shfl_xor_sync(0xffffffffu, m, 16));
        m = fmaxf(m, __shfl_xor_sync(0xffffffffu, m, 8));
        m = fmaxf(m, __shfl_xor_sync(0xffffffffu, m, 4));
        m = fmaxf(m, __shfl_xor_sync(0xffffffffu, m, 2));
        m = fmaxf(m, __shfl_xor_sync(0xffffffffu, m, 1));
        if (lane == 0) sRed[wid] = m;
        __syncthreads();
        if (tid == 0) {
            float mm = sRed[0];
            #pragma unroll
            for (int w = 1; w < 8; w++) mm = fmaxf(mm, sRed[w]);
            sBcast = mm;
        }
        __syncthreads();
    }
    const float rowmax = sBcast;
    float e = __expf(sE[tid] - rowmax);
    __syncthreads();   // protect sBcast reuse
    {
        float s = e;
        s += __shfl_xor_sync(0xffffffffu, s, 16);
        s += __shfl_xor_sync(0xffffffffu, s, 8);
        s += __shfl_xor_sync(0xffffffffu, s, 4);
        s += __shfl_xor_sync(0xffffffffu, s, 2);
        s += __shfl_xor_sync(0xffffffffu, s, 1);
        if (lane == 0) sRed[wid] = s;
        __syncthreads();
        if (tid == 0) {
            float ss = 0.f;
            #pragma unroll
            for (int w = 0; w < 8; w++) ss += sRed[w];
            sBcast = 1.0f / ss;
        }
        __syncthreads();
    }
    const float a = e * sBcast;
    sE[tid] = a;
    if (A_out) {
        A_out[((long long)(bh * L_DIM + q)) * L_DIM + tid] = a;
    }
    __syncthreads();

    // ---- phase 3: output row ----
    {
        const float2* pT = (const float2*)&tmV[tm_row  + (long long)kbase * D_DIM + 2 * lane];
        const float2* pV = (const float2*)&V  [kv_base + (long long)kbase * D_DIM + 2 * lane];
        float accx = 0.f, accy = 0.f;
        #pragma unroll 4
        for (int i = 0; i < 32; i++) {
            const float aw = sE[kbase + i];
            const float2 tv = pT[i * (D_DIM / 2)];
            const float2 vv = pV[i * (D_DIM / 2)];
            accx = fmaf(aw, vv.x + tv.x, accx);
            accy = fmaf(aw, vv.y + tv.y, accy);
        }
        sPart[wid][2 * lane]     = accx;
        sPart[wid][2 * lane + 1] = accy;
    }
    __syncthreads();

    if (tid < D_DIM) {
        float s = 0.f;
        #pragma unroll
        for (int w = 0; w < 8; w++) s += sPart[w][tid];
        O[row_qd + tid] = s;
    }
}

extern "C" void kernel_launch(void* const* d_in, const int* in_sizes, int n_in,
                              void* d_out, int out_size)
{
    const float* Q   = (const float*)d_in[0];
    const float* K   = (const float*)d_in[1];
    const float* V   = (const float*)d_in[2];
    const float* tmK = (const float*)d_in[3];
    const float* tmV = (const float*)d_in[4];
    const float* attn_mask = (const float*)d_in[5];
    const unsigned char* pad_mask = (const unsigned char*)d_in[6];

    const int L  = L_DIM;
    const int D  = D_DIM;
    const int BH = in_sizes[0] / (L * D);      // b*h
    const int B  = in_sizes[6] / L;            // padding_mask = (b, L)
    const int H  = BH / B;

    const long long O_elems = (long long)in_sizes[0];
    const long long A_elems = (long long)BH * L * L;

    float* O_out = (float*)d_out;
    float* A_out = ((long long)out_size >= O_elems + A_elems)
                       ? (float*)d_out + O_elems : nullptr;

    dim3 grid(L, BH);
    taspd_kernel<<<grid, 256>>>(Q, K, V, tmK, tmV, attn_mask, pad_mask,
                                O_out, A_out, H);
}